// round 15
// baseline (speedup 1.0000x reference)
#include <cuda_runtime.h>
#include <cuda_bf16.h>
#include <mma.h>
#include <cstdint>
#include <stdint.h>
#include <math.h>

using namespace nvcuda;

namespace lsgm {

constexpr int nB   = 4;
constexpr int nT   = 4096;
constexpr int nDIM = 1024;
constexpr int nHID = 1536;
constexpr int nHID2 = 3072;
constexpr int nS   = 16;
constexpr int nD   = 384;
constexpr int nL   = 256;
constexpr int nM   = nB * nT;       // 16384
constexpr int CH   = 64;            // scan chunk length
constexpr int NG   = nT / CH;       // 64 chunks
constexpr int nHP  = nHID / 2;      // 768 pairs per row
constexpr long long NPAIRS_H = (long long)nM * nHP;

constexpr float INV_SQRT_D = 0.05103103630798287f;   // 1/sqrt(384)

// ---------------- scratch (static device globals; no runtime alloc) ----------------
__device__ float g_proj [(size_t)nM * nHID2];
__device__ float g_xh1  [(size_t)nM * nHID];
__device__ float g_gbuf [(size_t)nM * nHID2];
__device__ float g_alpha[(size_t)nM * nHID];
__device__ float g_xh2  [(size_t)nM * nHID];
__device__ float g_hbuf [(size_t)nM * nHID];
__device__ float g_xh3  [(size_t)nM * nHID];
__device__ float g_rq   [(size_t)nM * nD];
__device__ float g_qk   [nM];
__device__ float g_xg   [nM];
__device__ float g_q    [nS * nD];
__device__ float g_qw   [nS * nHID];
__device__ float g_u    [nB * nS * nHID];
__device__ float g_mem  [nB * nS * nD];
__device__ float g_rk   [nB * nS * nD];
__device__ float g_rv   [nB * nS * nHID];
__device__ float g_cA   [nB * NG * nHID];
__device__ float g_cB   [nB * NG * nHID];
__device__ float g_carry[nB * NG * nHID];

// bf16 hi/lo buffers: [R*K hi bf16][R*K lo bf16]
__device__ __align__(128) unsigned g_cx  [(size_t)nM * nDIM];
__device__ __align__(128) unsigned g_cxh1[(size_t)nM * nHID];
__device__ __align__(128) unsigned g_cxr [(size_t)nM * nHID];
__device__ __align__(128) unsigned g_cog [(size_t)nM * nHID];
__device__ __align__(128) unsigned g_ciw [(size_t)nHID2 * nDIM];
__device__ __align__(128) unsigned g_cgw [(size_t)nHID2 * nHID];
__device__ __align__(128) unsigned g_crqw[(size_t)nD * nHID];
__device__ __align__(128) unsigned g_cow [(size_t)nDIM * nHID];

// ==================== cp.async helpers ====================
__device__ __forceinline__ uint32_t smem_u32(const void* p) {
    uint32_t a;
    asm("{ .reg .u64 t; cvta.to.shared.u64 t, %1; cvt.u32.u64 %0, t; }" : "=r"(a) : "l"(p));
    return a;
}
__device__ __forceinline__ void cp16(void* sp, const void* gp) {
    uint32_t s = smem_u32(sp);
    asm volatile("cp.async.cg.shared.global [%0], [%1], 16;" :: "r"(s), "l"(gp) : "memory");
}
__device__ __forceinline__ void cp_commit() {
    asm volatile("cp.async.commit_group;" ::: "memory");
}
template<int N> __device__ __forceinline__ void cp_wait() {
    asm volatile("cp.async.wait_group %0;" :: "n"(N) : "memory");
}

// pack two fp32 into bf16 hi word + bf16 residual (lo) word
__device__ __forceinline__ void cvt_pair(float x, float y, unsigned& hi, unsigned& lo) {
    unsigned ux = __float_as_uint(x), uy = __float_as_uint(y);
    hi = __byte_perm(ux, uy, 0x7632);
    float rx = x - __uint_as_float(ux & 0xFFFF0000u);
    float ry = y - __uint_as_float(uy & 0xFFFF0000u);
    asm("cvt.rn.bf16x2.f32 %0, %1, %2;" : "=r"(lo) : "f"(ry), "f"(rx));
}

// ==================== fp32 -> bf16 hi/lo converter ====================
__global__ void k_cvt(const float* __restrict__ src, unsigned* __restrict__ dst,
                      long long npairs)
{
    long long i = (long long)blockIdx.x * blockDim.x + threadIdx.x;
    if (i >= npairs) return;
    float2 v = *(const float2*)(src + 2 * i);
    unsigned hi, lo;
    cvt_pair(v.x, v.y, hi, lo);
    dst[i] = hi;
    dst[npairs + i] = lo;
}

// ==================== wgemm: 128x128 CTA tile (used for N=384 only) ====================
constexpr int TSTRIDE = 40;
constexpr int MAT_ELEMS = 128 * TSTRIDE;
constexpr int WG_SMEM = 2 * 4 * MAT_ELEMS * 2;                 // 81920 bytes

__global__ __launch_bounds__(256, 2) void wgemm(
    const unsigned* __restrict__ Ac, const unsigned* __restrict__ Bc,
    float* __restrict__ C, int M, int N, int Kd)
{
    extern __shared__ __align__(16) __nv_bfloat16 dbuf[];

    const __nv_bfloat16* src[4];
    src[0] = (const __nv_bfloat16*)Ac;
    src[1] = src[0] + (size_t)M * Kd;
    src[2] = (const __nv_bfloat16*)Bc;
    src[3] = src[2] + (size_t)N * Kd;

    const int tid = threadIdx.x;
    const int bm = blockIdx.y << 7, bn = blockIdx.x << 7;
    const int w = tid >> 5;
    const int wm = (w & 3) * 32;
    const int wn = (w >> 2) * 64;

    const int lr = tid >> 2;
    const int lc = (tid & 3) << 3;

    const int rbase[4] = {bm, bm, bn, bn};

    wmma::fragment<wmma::accumulator, 16, 16, 16, float> acc[2][4];
#pragma unroll
    for (int i = 0; i < 2; i++)
#pragma unroll
        for (int j = 0; j < 4; j++) wmma::fill_fragment(acc[i][j], 0.f);

    const int nk = Kd >> 5;

#pragma unroll
    for (int m = 0; m < 4; m++) {
#pragma unroll
        for (int off = 0; off < 128; off += 64) {
            int row = lr + off;
            cp16(dbuf + m * MAT_ELEMS + row * TSTRIDE + lc,
                 src[m] + (size_t)(rbase[m] + row) * Kd + lc);
        }
    }
    cp_commit();

    for (int ki = 0; ki < nk; ki++) {
        int st = ki & 1;
        if (ki + 1 < nk) {
            int ns = (ki + 1) & 1;
            int k0 = (ki + 1) << 5;
#pragma unroll
            for (int m = 0; m < 4; m++) {
#pragma unroll
                for (int off = 0; off < 128; off += 64) {
                    int row = lr + off;
                    cp16(dbuf + (ns * 4 + m) * MAT_ELEMS + row * TSTRIDE + lc,
                         src[m] + (size_t)(rbase[m] + row) * Kd + k0 + lc);
                }
            }
            cp_commit();
            cp_wait<1>();
        } else {
            cp_wait<0>();
        }
        __syncthreads();

        const __nv_bfloat16* tAh = dbuf + (st * 4 + 0) * MAT_ELEMS;
        const __nv_bfloat16* tAl = dbuf + (st * 4 + 1) * MAT_ELEMS;
        const __nv_bfloat16* tBh = dbuf + (st * 4 + 2) * MAT_ELEMS;
        const __nv_bfloat16* tBl = dbuf + (st * 4 + 3) * MAT_ELEMS;

#pragma unroll
        for (int kk = 0; kk < 32; kk += 16) {
            wmma::fragment<wmma::matrix_a, 16, 16, 16, __nv_bfloat16, wmma::row_major> ah[2], al[2];
#pragma unroll
            for (int i = 0; i < 2; i++) {
                wmma::load_matrix_sync(ah[i], tAh + (wm + 16 * i) * TSTRIDE + kk, TSTRIDE);
                wmma::load_matrix_sync(al[i], tAl + (wm + 16 * i) * TSTRIDE + kk, TSTRIDE);
            }
#pragma unroll
            for (int j = 0; j < 4; j++) {
                wmma::fragment<wmma::matrix_b, 16, 16, 16, __nv_bfloat16, wmma::col_major> bh, bl;
                wmma::load_matrix_sync(bh, tBh + (wn + 16 * j) * TSTRIDE + kk, TSTRIDE);
                wmma::load_matrix_sync(bl, tBl + (wn + 16 * j) * TSTRIDE + kk, TSTRIDE);
#pragma unroll
                for (int i = 0; i < 2; i++) {
                    wmma::mma_sync(acc[i][j], ah[i], bh, acc[i][j]);
                    wmma::mma_sync(acc[i][j], ah[i], bl, acc[i][j]);
                    wmma::mma_sync(acc[i][j], al[i], bh, acc[i][j]);
                }
            }
        }
        __syncthreads();
    }
#pragma unroll
    for (int i = 0; i < 2; i++)
#pragma unroll
        for (int j = 0; j < 4; j++) {
            float* cp = C + (size_t)(bm + wm + 16 * i) * N + bn + wn + 16 * j;
            wmma::store_matrix_sync(cp, acc[i][j], N, wmma::mem_row_major);
        }
}

// ==================== wgemm256: 128x256 CTA tile, warp tile 64x64 ====================
// 8 warps = 2(M) x 4(N). MMA:fragload = 48:16 per kk. smem 60KB/stage x2 = 120KB.
constexpr int A_EL   = 128 * TSTRIDE;          // per A matrix (hi or lo)
constexpr int B_EL   = 256 * TSTRIDE;          // per B matrix
constexpr int ST_EL  = 2 * A_EL + 2 * B_EL;    // halves per stage = 30720
constexpr int WG2_SMEM = 2 * ST_EL * 2;        // 122880 bytes

__global__ __launch_bounds__(256, 1) void wgemm256(
    const unsigned* __restrict__ Ac, const unsigned* __restrict__ Bc,
    float* __restrict__ C, int M, int N, int Kd)
{
    extern __shared__ __align__(16) __nv_bfloat16 dbuf[];

    const __nv_bfloat16* Ah = (const __nv_bfloat16*)Ac;
    const __nv_bfloat16* Al = Ah + (size_t)M * Kd;
    const __nv_bfloat16* Bh = (const __nv_bfloat16*)Bc;
    const __nv_bfloat16* Bl = Bh + (size_t)N * Kd;

    const int tid = threadIdx.x;
    const int bm = blockIdx.y << 7, bn = blockIdx.x << 8;
    const int w = tid >> 5;
    const int wm = (w & 1) * 64;        // 2 warps in M
    const int wn = (w >> 1) * 64;       // 4 warps in N

    // loader indices
    const int ar = tid >> 1;            // 0..127 (A row)
    const int ac = (tid & 1) << 4;      // 0 or 16

    wmma::fragment<wmma::accumulator, 16, 16, 16, float> acc[4][4];
#pragma unroll
    for (int i = 0; i < 4; i++)
#pragma unroll
        for (int j = 0; j < 4; j++) wmma::fill_fragment(acc[i][j], 0.f);

    const int nk = Kd >> 5;

    // ---- stage loader ----
    auto load_stage = [&](int stg, int k0) {
        __nv_bfloat16* sb = dbuf + stg * ST_EL;
        // A hi / A lo: thread -> row ar, halves [ac, ac+16)
        const __nv_bfloat16* ga = Ah + (size_t)(bm + ar) * Kd + k0 + ac;
        const __nv_bfloat16* gl = Al + (size_t)(bm + ar) * Kd + k0 + ac;
        cp16(sb + ar * TSTRIDE + ac,                ga);
        cp16(sb + ar * TSTRIDE + ac + 8,            ga + 8);
        cp16(sb + A_EL + ar * TSTRIDE + ac,         gl);
        cp16(sb + A_EL + ar * TSTRIDE + ac + 8,     gl + 8);
        // B hi / B lo: thread -> row tid, 32 halves
        const __nv_bfloat16* gb = Bh + (size_t)(bn + tid) * Kd + k0;
        const __nv_bfloat16* gc = Bl + (size_t)(bn + tid) * Kd + k0;
        __nv_bfloat16* sbh = sb + 2 * A_EL + tid * TSTRIDE;
        __nv_bfloat16* sbl = sbh + B_EL;
#pragma unroll
        for (int q = 0; q < 4; q++) {
            cp16(sbh + q * 8, gb + q * 8);
            cp16(sbl + q * 8, gc + q * 8);
        }
    };

    load_stage(0, 0);
    cp_commit();

    for (int ki = 0; ki < nk; ki++) {
        int st = ki & 1;
        if (ki + 1 < nk) {
            load_stage((ki + 1) & 1, (ki + 1) << 5);
            cp_commit();
            cp_wait<1>();
        } else {
            cp_wait<0>();
        }
        __syncthreads();

        const __nv_bfloat16* tAh = dbuf + st * ST_EL;
        const __nv_bfloat16* tAl = tAh + A_EL;
        const __nv_bfloat16* tBh = tAh + 2 * A_EL;
        const __nv_bfloat16* tBl = tBh + B_EL;

#pragma unroll
        for (int kk = 0; kk < 32; kk += 16) {
            wmma::fragment<wmma::matrix_a, 16, 16, 16, __nv_bfloat16, wmma::row_major> ah[4], al[4];
#pragma unroll
            for (int i = 0; i < 4; i++) {
                wmma::load_matrix_sync(ah[i], tAh + (wm + 16 * i) * TSTRIDE + kk, TSTRIDE);
                wmma::load_matrix_sync(al[i], tAl + (wm + 16 * i) * TSTRIDE + kk, TSTRIDE);
            }
#pragma unroll
            for (int j = 0; j < 4; j++) {
                wmma::fragment<wmma::matrix_b, 16, 16, 16, __nv_bfloat16, wmma::col_major> bh, bl;
                wmma::load_matrix_sync(bh, tBh + (wn + 16 * j) * TSTRIDE + kk, TSTRIDE);
                wmma::load_matrix_sync(bl, tBl + (wn + 16 * j) * TSTRIDE + kk, TSTRIDE);
#pragma unroll
                for (int i = 0; i < 4; i++) {
                    wmma::mma_sync(acc[i][j], ah[i], bh, acc[i][j]);
                    wmma::mma_sync(acc[i][j], ah[i], bl, acc[i][j]);
                    wmma::mma_sync(acc[i][j], al[i], bh, acc[i][j]);
                }
            }
        }
        __syncthreads();
    }
#pragma unroll
    for (int i = 0; i < 4; i++)
#pragma unroll
        for (int j = 0; j < 4; j++) {
            float* cp = C + (size_t)(bm + wm + 16 * i) * N + bn + wn + 16 * j;
            wmma::store_matrix_sync(cp, acc[i][j], N, wmma::mem_row_major);
        }
}

// ==================== elementwise / small kernels (unchanged) ====================
__global__ void k_qproj(const float* __restrict__ ms, const float* __restrict__ wq)
{
    int n = blockIdx.x * blockDim.x + threadIdx.x;
    if (n >= nS * nD) return;
    int s = n / nD, d = n % nD;
    const float* mp = ms + (size_t)s * nD;
    const float* wp = wq + (size_t)d * nD;
    float a = 0.f;
#pragma unroll 4
    for (int e = 0; e < nD; e++) a += mp[e] * wp[e];
    g_q[n] = a;
}

__global__ void k_qwproj(const float* __restrict__ wk)
{
    int n = blockIdx.x * blockDim.x + threadIdx.x;
    if (n >= nS * nHID) return;
    int s = n / nHID, h = n % nHID;
    float a = 0.f;
#pragma unroll 4
    for (int d = 0; d < nD; d++) a += g_q[s * nD + d] * wk[(size_t)d * nHID + h];
    g_qw[n] = a;
}

__global__ void k_conv(const float* __restrict__ cw, const float* __restrict__ cb)
{
    int i = blockIdx.x * blockDim.x + threadIdx.x;
    if (i >= (nM / 4) * nHP) return;
    int hp = i % nHP;
    int mq = i / nHP;
    int h  = hp * 2;
    int m0 = mq * 4;
    int t0 = m0 & (nT - 1);
    const float* p = g_proj + (size_t)m0 * nHID2 + nHID + h;
    const long long st = nHID2;
    float2 xv[7];
    const float2 z2 = make_float2(0.f, 0.f);
    xv[0] = (t0 >= 3) ? *(const float2*)(p - 3 * st) : z2;
    xv[1] = (t0 >= 2) ? *(const float2*)(p - 2 * st) : z2;
    xv[2] = (t0 >= 1) ? *(const float2*)(p - 1 * st) : z2;
    xv[3] = *(const float2*)(p);
    xv[4] = *(const float2*)(p + 1 * st);
    xv[5] = *(const float2*)(p + 2 * st);
    xv[6] = *(const float2*)(p + 3 * st);
    float4 wa = *(const float4*)(cw + h * 4);
    float4 wb = *(const float4*)(cw + (h + 1) * 4);
    float2 bb = *(const float2*)(cb + h);
    float* op = g_xh1 + (size_t)m0 * nHID + h;
#pragma unroll
    for (int k = 0; k < 4; k++) {
        float o0 = bb.x + wa.x * xv[k].x + wa.y * xv[k + 1].x + wa.z * xv[k + 2].x + wa.w * xv[k + 3].x;
        float o1 = bb.y + wb.x * xv[k].y + wb.y * xv[k + 1].y + wb.z * xv[k + 2].y + wb.w * xv[k + 3].y;
        *(float2*)(op + (size_t)k * nHID) = make_float2(o0, o1);
        unsigned hi, lo;
        cvt_pair(o0, o1, hi, lo);
        long long pidx = (long long)(m0 + k) * nHP + hp;
        g_cxh1[pidx] = hi;
        g_cxh1[NPAIRS_H + pidx] = lo;
    }
}

__global__ void k_scan1(const float* __restrict__ fb, const float* __restrict__ gb)
{
    int n = blockIdx.x * blockDim.x + threadIdx.x;
    if (n >= nB * NG * nHID) return;
    int b = n / (NG * nHID);
    int r = n - b * NG * nHID;
    int g = r / nHID;
    int h = r - g * nHID;
    size_t m0 = (size_t)b * nT + (size_t)g * CH;
    float c   = -8.f * log1pf(expf(fb[h]));
    float gbf = gb[h], gbi = gb[nHID + h];
    float A = 1.f, Bv = 0.f;
    size_t idxg = m0 * nHID2 + h;
    size_t idxh = m0 * nHID + h;
#pragma unroll 2
    for (int i = 0; i < CH; i++) {
        float f  = g_gbuf[idxg] + gbf;
        float ip = g_gbuf[idxg + nHID] + gbi;
        float sf = 1.f / (1.f + expf(-f));
        float a  = expf(c * sf);
        float si = 1.f / (1.f + expf(-ip));
        float x  = sqrtf(1.f - a * a + 1e-6f) * si * g_xh1[idxh];
        g_alpha[idxh] = a;
        g_xh2[idxh]   = x;
        Bv = a * Bv + x;
        A *= a;
        idxg += nHID2;
        idxh += nHID;
    }
    g_cA[n] = A; g_cB[n] = Bv;
}

__global__ void k_scan2()
{
    int n = blockIdx.x * blockDim.x + threadIdx.x;
    if (n >= nB * nHID) return;
    int b = n / nHID;
    int h = n - b * nHID;
    float s = 0.f;
    for (int g = 0; g < NG; g++) {
        int j = (b * NG + g) * nHID + h;
        g_carry[j] = s;
        s = g_cA[j] * s + g_cB[j];
    }
}

__global__ void k_scan3()
{
    int n = blockIdx.x * blockDim.x + threadIdx.x;
    if (n >= nB * NG * nHID) return;
    int b = n / (NG * nHID);
    int r = n - b * NG * nHID;
    int g = r / nHID;
    int h = r - g * nHID;
    size_t idx = ((size_t)b * nT + (size_t)g * CH) * nHID + h;
    float run = g_carry[n];
#pragma unroll 4
    for (int i = 0; i < CH; i++) {
        run = g_alpha[idx] * run + g_xh2[idx];
        g_hbuf[idx] = run;
        idx += nHID;
    }
}

__global__ __launch_bounds__(256) void k_fuse(const float* __restrict__ wg)
{
    int m = blockIdx.x;
    int tid = threadIdx.x;
    int t = m & (nT - 1);
    int s = t >> 8;
    __shared__ float r1[256], r2[256];
    float qkp = 0.f, xgp = 0.f;
    for (int p = tid; p < nHP; p += 256) {
        int h = 2 * p;
        float2 gt = *(const float2*)(g_proj + (size_t)m * nHID2 + h);
        float2 x2 = *(const float2*)(g_xh2 + (size_t)m * nHID + h);
        float2 hv = *(const float2*)(g_hbuf + (size_t)m * nHID + h);
        float x3a = gt.x * (1.f / (1.f + expf(-gt.x))) * x2.x;
        float x3b = gt.y * (1.f / (1.f + expf(-gt.y))) * x2.y;
        float xra = 0.5f * x3a * (1.f + erff(x3a * 0.7071067811865476f)) * hv.x;
        float xrb = 0.5f * x3b * (1.f + erff(x3b * 0.7071067811865476f)) * hv.y;
        *(float2*)(g_xh3 + (size_t)m * nHID + h) = make_float2(x3a, x3b);
        unsigned hi, lo;
        cvt_pair(xra, xrb, hi, lo);
        long long pidx = (long long)m * nHP + p;
        g_cxr[pidx] = hi;
        g_cxr[NPAIRS_H + pidx] = lo;
        float2 qw2 = *(const float2*)(g_qw + s * nHID + h);
        float2 wg2 = *(const float2*)(wg + h);
        qkp += qw2.x * x3a + qw2.y * x3b;
        xgp += wg2.x * xra + wg2.y * xrb;
    }
    r1[tid] = qkp; r2[tid] = xgp;
    __syncthreads();
    for (int o = 128; o > 0; o >>= 1) {
        if (tid < o) { r1[tid] += r1[tid + o]; r2[tid] += r2[tid + o]; }
        __syncthreads();
    }
    if (tid == 0) { g_qk[m] = r1[0] * INV_SQRT_D; g_xg[m] = r2[0]; }
}

__global__ __launch_bounds__(256) void k_segsoft()
{
    int bs = blockIdx.x;
    int hb = blockIdx.y;
    int tid = threadIdx.x;
    int b = bs >> 4, s = bs & 15;
    size_t base = (size_t)b * nT + (size_t)s * nL;
    __shared__ float at[256];
    __shared__ float red[256];
    float v = g_qk[base + tid];
    red[tid] = v; __syncthreads();
    for (int o = 128; o > 0; o >>= 1) {
        if (tid < o) red[tid] = fmaxf(red[tid], red[tid + o]);
        __syncthreads();
    }
    float mx = red[0];
    __syncthreads();
    float e = expf(v - mx);
    red[tid] = e; __syncthreads();
    for (int o = 128; o > 0; o >>= 1) {
        if (tid < o) red[tid] += red[tid + o];
        __syncthreads();
    }
    at[tid] = e / red[0];
    __syncthreads();
    int h = hb * 256 + tid;
    const float* xp = g_xh3 + base * nHID + h;
    float a0 = 0.f, a1 = 0.f, a2 = 0.f, a3 = 0.f;
    for (int l = 0; l < nL; l += 4) {
        a0 += at[l + 0] * xp[(size_t)(l + 0) * nHID];
        a1 += at[l + 1] * xp[(size_t)(l + 1) * nHID];
        a2 += at[l + 2] * xp[(size_t)(l + 2) * nHID];
        a3 += at[l + 3] * xp[(size_t)(l + 3) * nHID];
    }
    g_u[(size_t)bs * nHID + h] = (a0 + a1) + (a2 + a3);
}

__global__ void k_memproj(const float* __restrict__ wv)
{
    int n = blockIdx.x * blockDim.x + threadIdx.x;
    if (n >= nB * nS * nD) return;
    int bs = n / nD, d = n % nD;
    const float* up = g_u + (size_t)bs * nHID;
    const float* wp = wv + (size_t)d * nHID;
    float a = 0.f;
#pragma unroll 4
    for (int h = 0; h < nHID; h++) a += wp[h] * up[h];
    g_mem[n] = a;
}

__global__ void k_rkproj(const float* __restrict__ rkw)
{
    int n = blockIdx.x * blockDim.x + threadIdx.x;
    if (n >= nB * nS * nD) return;
    int bs = n / nD, d = n % nD;
    const float* mp = g_mem + (size_t)bs * nD;
    const float* wp = rkw + (size_t)d * nD;
    float a = 0.f;
#pragma unroll 4
    for (int e = 0; e < nD; e++) a += mp[e] * wp[e];
    g_rk[n] = a;
}

__global__ void k_rvproj(const float* __restrict__ rvw)
{
    int n = blockIdx.x * blockDim.x + threadIdx.x;
    if (n >= nB * nS * nHID) return;
    int bs = n / nHID, h = n % nHID;
    const float* mp = g_mem + (size_t)bs * nD;
    const float* wp = rvw + (size_t)h * nD;
    float a = 0.f;
#pragma unroll 4
    for (int d = 0; d < nD; d++) a += mp[d] * wp[d];
    g_rv[n] = a;
}

__global__ __launch_bounds__(128) void k_attn2()
{
    int m0 = blockIdx.x * 4;
    int b = m0 / nT, t0 = m0 % nT;
    int seg = t0 >> 8;
    int tid = threadIdx.x;
    __shared__ float rqs[4][nD];
    __shared__ float sc[4][nS];
    __shared__ float a2s[4][nS];
    __shared__ float gv[4];
    for (int i = tid; i < 4 * nD; i += 128)
        rqs[i / nD][i % nD] = g_rq[(size_t)m0 * nD + i];
    __syncthreads();
    int warp = tid >> 5, lane = tid & 31;
    for (int s = warp; s < nS; s += 4) {
        const float* rkp = g_rk + (size_t)(b * nS + s) * nD;
        float p0 = 0.f, p1 = 0.f, p2 = 0.f, p3 = 0.f;
        for (int d = lane; d < nD; d += 32) {
            float rv = rkp[d];
            p0 += rqs[0][d] * rv;
            p1 += rqs[1][d] * rv;
            p2 += rqs[2][d] * rv;
            p3 += rqs[3][d] * rv;
        }
#pragma unroll
        for (int o = 16; o > 0; o >>= 1) {
            p0 += __shfl_xor_sync(0xffffffffu, p0, o);
            p1 += __shfl_xor_sync(0xffffffffu, p1, o);
            p2 += __shfl_xor_sync(0xffffffffu, p2, o);
            p3 += __shfl_xor_sync(0xffffffffu, p3, o);
        }
        if (lane == 0) {
            sc[0][s] = p0 * INV_SQRT_D;
            sc[1][s] = p1 * INV_SQRT_D;
            sc[2][s] = p2 * INV_SQRT_D;
            sc[3][s] = p3 * INV_SQRT_D;
        }
    }
    __syncthreads();
    if (tid < 4) {
        int tt = tid;
        float mx = -1e30f;
        for (int s = seg; s < nS; s++) mx = fmaxf(mx, sc[tt][s]);
        float sum = 0.f;
        for (int s = 0; s < nS; s++) {
            float e = (s >= seg) ? expf(sc[tt][s] - mx) : 0.f;
            a2s[tt][s] = e; sum += e;
        }
        float inv = 1.f / sum;
        for (int s = 0; s < nS; s++) a2s[tt][s] *= inv;
        gv[tt] = 1.f / (1.f + expf(-g_xg[m0 + tt]));
    }
    __syncthreads();
    for (int p = tid; p < nHP; p += 128) {
        int h = 2 * p;
        float ax[4], ay[4];
#pragma unroll
        for (int tt = 0; tt < 4; tt++) { ax[tt] = 0.f; ay[tt] = 0.f; }
#pragma unroll
        for (int s = 0; s < nS; s++) {
            float2 rv2 = *(const float2*)(g_rv + (size_t)(b * nS + s) * nHID + h);
#pragma unroll
            for (int tt = 0; tt < 4; tt++) {
                ax[tt] += a2s[tt][s] * rv2.x;
                ay[tt] += a2s[tt][s] * rv2.y;
            }
        }
#pragma unroll
        for (int tt = 0; tt < 4; tt++) {
            unsigned hi, lo;
            cvt_pair(gv[tt] * ax[tt], gv[tt] * ay[tt], hi, lo);
            long long pidx = (long long)(m0 + tt) * nHP + p;
            g_cog[pidx] = hi;
            g_cog[NPAIRS_H + pidx] = lo;
        }
    }
}

} // namespace lsgm

extern "C" void kernel_launch(void* const* d_in, const int* in_sizes, int n_in,
                              void* d_out, int out_size)
{
    using namespace lsgm;
    const float* x        = (const float*)d_in[0];
    const float* input_w  = (const float*)d_in[1];
    const float* conv_w   = (const float*)d_in[2];
    const float* conv_b   = (const float*)d_in[3];
    const float* gates_w  = (const float*)d_in[4];
    const float* gates_b  = (const float*)d_in[5];
    const float* fbase    = (const float*)d_in[6];
    const float* output_w = (const float*)d_in[7];
    const float* mslots   = (const float*)d_in[8];
    const float* wq_w     = (const float*)d_in[9];
    const float* wk_w     = (const float*)d_in[10];
    const float* wv_w     = (const float*)d_in[11];
    const float* wg_w     = (const float*)d_in[12];
    const float* rq_w     = (const float*)d_in[13];
    const float* rk_w     = (const float*)d_in[14];
    const float* rv_w     = (const float*)d_in[15];
    float* out = (float*)d_out;

    float* proj_p; cudaGetSymbolAddress((void**)&proj_p, g_proj);
    float* gbuf_p; cudaGetSymbolAddress((void**)&gbuf_p, g_gbuf);
    float* rq_p;   cudaGetSymbolAddress((void**)&rq_p,   g_rq);
    unsigned *cx_p, *cxh1_p, *cxr_p, *cog_p, *ciw_p, *cgw_p, *crqw_p, *cow_p;
    cudaGetSymbolAddress((void**)&cx_p,   g_cx);
    cudaGetSymbolAddress((void**)&cxh1_p, g_cxh1);
    cudaGetSymbolAddress((void**)&cxr_p,  g_cxr);
    cudaGetSymbolAddress((void**)&cog_p,  g_cog);
    cudaGetSymbolAddress((void**)&ciw_p,  g_ciw);
    cudaGetSymbolAddress((void**)&cgw_p,  g_cgw);
    cudaGetSymbolAddress((void**)&crqw_p, g_crqw);
    cudaGetSymbolAddress((void**)&cow_p,  g_cow);

    cudaFuncSetAttribute(wgemm,    cudaFuncAttributeMaxDynamicSharedMemorySize, WG_SMEM);
    cudaFuncSetAttribute(wgemm256, cudaFuncAttributeMaxDynamicSharedMemorySize, WG2_SMEM);

    auto cvt = [&](const float* s, unsigned* d, int R, int Kd) {
        long long pairs = (long long)R * Kd / 2;
        k_cvt<<<(unsigned)((pairs + 255) / 256), 256>>>(s, d, pairs);
    };

    // weight conversions + memory-slot query path
    cvt(input_w,  ciw_p,  nHID2, nDIM);
    cvt(gates_w,  cgw_p,  nHID2, nHID);
    cvt(rq_w,     crqw_p, nD,    nHID);
    cvt(output_w, cow_p,  nDIM,  nHID);
    k_qproj <<<(nS * nD + 255) / 256, 256>>>(mslots, wq_w);
    k_qwproj<<<(nS * nHID + 255) / 256, 256>>>(wk_w);

    // proj = x @ input_w^T  -> [M, 3072]
    cvt(x, cx_p, nM, nDIM);
    wgemm256<<<dim3(nHID2 / 256, nM / 128), 256, WG2_SMEM>>>(cx_p, ciw_p, proj_p, nM, nHID2, nDIM);

    // causal depthwise conv (fp32 + bf16 hi/lo)
    k_conv<<<((nM / 4) * nHP + 255) / 256, 256>>>(conv_w, conv_b);

    // gates = xh1 @ gates_w^T (bias folded into scan1) -> [M, 3072]
    wgemm256<<<dim3(nHID2 / 256, nM / 128), 256, WG2_SMEM>>>(cxh1_p, cgw_p, gbuf_p, nM, nHID2, nHID);

    // chunked scan
    k_scan1<<<(nB * NG * nHID) / 256, 256>>>(fbase, gates_b);
    k_scan2<<<(nB * nHID) / 256, 256>>>();
    k_scan3<<<(nB * NG * nHID) / 256, 256>>>();

    // xh3, xr(->bf16), qk dot, wg dot
    k_fuse<<<nM, 256>>>(wg_w);

    // slot attention + tiny projections
    k_segsoft<<<dim3(nB * nS, nHID / 256), 256>>>();
    k_memproj<<<(nB * nS * nD) / 256, 256>>>(wv_w);
    k_rkproj <<<(nB * nS * nD) / 256, 256>>>(rk_w);
    k_rvproj <<<(nB * nS * nHID) / 256, 256>>>(rv_w);

    // rq = xr @ rq_w^T -> [M, 384]  (N=384 not divisible by 256 -> 128x128 kernel)
    wgemm<<<dim3(nD / 128, nM / 128), 256, WG_SMEM>>>(cxr_p, crqw_p, rq_p, nM, nD, nHID);

    // cross-segment attention + output gate (4 tokens/block)
    k_attn2<<<nM / 4, 128>>>();

    // final: out = outg @ output_w^T -> [M, 1024]
    wgemm256<<<dim3(nDIM / 256, nM / 128), 256, WG2_SMEM>>>(cog_p, cow_p, out, nM, nDIM, nHID);
}

// round 17
// speedup vs baseline: 1.2899x; 1.2899x over previous
#include <cuda_runtime.h>
#include <cuda_bf16.h>
#include <mma.h>
#include <cstdint>
#include <stdint.h>
#include <math.h>

using namespace nvcuda;

namespace lsgm {

constexpr int nB   = 4;
constexpr int nT   = 4096;
constexpr int nDIM = 1024;
constexpr int nHID = 1536;
constexpr int nHID2 = 3072;
constexpr int nS   = 16;
constexpr int nD   = 384;
constexpr int nL   = 256;
constexpr int nM   = nB * nT;       // 16384
constexpr int CH   = 64;            // scan chunk length
constexpr int NG   = nT / CH;       // 64 chunks
constexpr int nHP  = nHID / 2;      // 768 pairs per row
constexpr long long NPAIRS_H = (long long)nM * nHP;

constexpr float INV_SQRT_D = 0.05103103630798287f;   // 1/sqrt(384)

// ---------------- scratch (static device globals; no runtime alloc) ----------------
__device__ float g_proj [(size_t)nM * nHID2];
__device__ float g_gbuf [(size_t)nM * nHID2];
__device__ float g_alpha[(size_t)nM * nHID];
__device__ float g_xh2  [(size_t)nM * nHID];
__device__ float g_hbuf [(size_t)nM * nHID];
__device__ float g_xh3  [(size_t)nM * nHID];
__device__ float g_rq   [(size_t)nM * nD];
__device__ float g_qk   [nM];
__device__ float g_xg   [nM];
__device__ float g_q    [nS * nD];
__device__ float g_qw   [nS * nHID];
__device__ float g_u    [nB * nS * nHID];
__device__ float g_mem  [nB * nS * nD];
__device__ float g_rk   [nB * nS * nD];
__device__ float g_rv   [nB * nS * nHID];
__device__ float g_cA   [nB * NG * nHID];
__device__ float g_cB   [nB * NG * nHID];
__device__ float g_carry[nB * NG * nHID];

// bf16 hi/lo buffers: [R*K hi bf16][R*K lo bf16]
__device__ __align__(128) unsigned g_cx  [(size_t)nM * nDIM];
__device__ __align__(128) unsigned g_cxh1[(size_t)nM * nHID];
__device__ __align__(128) unsigned g_cxr [(size_t)nM * nHID];
__device__ __align__(128) unsigned g_cog [(size_t)nM * nHID];
__device__ __align__(128) unsigned g_ciw [(size_t)nHID2 * nDIM];
__device__ __align__(128) unsigned g_cgw [(size_t)nHID2 * nHID];
__device__ __align__(128) unsigned g_crqw[(size_t)nD * nHID];
__device__ __align__(128) unsigned g_cow [(size_t)nDIM * nHID];

// ==================== cp.async helpers ====================
__device__ __forceinline__ uint32_t smem_u32(const void* p) {
    uint32_t a;
    asm("{ .reg .u64 t; cvta.to.shared.u64 t, %1; cvt.u32.u64 %0, t; }" : "=r"(a) : "l"(p));
    return a;
}
__device__ __forceinline__ void cp16(void* sp, const void* gp) {
    uint32_t s = smem_u32(sp);
    asm volatile("cp.async.cg.shared.global [%0], [%1], 16;" :: "r"(s), "l"(gp) : "memory");
}
__device__ __forceinline__ void cp_commit() {
    asm volatile("cp.async.commit_group;" ::: "memory");
}
template<int N> __device__ __forceinline__ void cp_wait() {
    asm volatile("cp.async.wait_group %0;" :: "n"(N) : "memory");
}

// pack two fp32 into bf16 hi word + bf16 residual (lo) word
__device__ __forceinline__ void cvt_pair(float x, float y, unsigned& hi, unsigned& lo) {
    unsigned ux = __float_as_uint(x), uy = __float_as_uint(y);
    hi = __byte_perm(ux, uy, 0x7632);          // {y_hi16 : x_hi16}
    float rx = x - __uint_as_float(ux & 0xFFFF0000u);
    float ry = y - __uint_as_float(uy & 0xFFFF0000u);
    asm("cvt.rn.bf16x2.f32 %0, %1, %2;" : "=r"(lo) : "f"(ry), "f"(rx));
}

// ==================== fp32 -> bf16 hi/lo converter ====================
__global__ void k_cvt(const float* __restrict__ src, unsigned* __restrict__ dst,
                      long long npairs)
{
    long long i = (long long)blockIdx.x * blockDim.x + threadIdx.x;
    if (i >= npairs) return;
    float2 v = *(const float2*)(src + 2 * i);
    unsigned hi, lo;
    cvt_pair(v.x, v.y, hi, lo);
    dst[i] = hi;
    dst[npairs + i] = lo;
}

// ==================== wmma bf16x3 GEMM with cp.async 2-stage pipeline ====================
constexpr int TSTRIDE = 40;
constexpr int MAT_ELEMS = 128 * TSTRIDE;
constexpr int WG_SMEM = 2 * 4 * MAT_ELEMS * 2;                 // 81920 bytes

__global__ __launch_bounds__(256, 2) void wgemm(
    const unsigned* __restrict__ Ac, const unsigned* __restrict__ Bc,
    float* __restrict__ C, int M, int N, int Kd)
{
    extern __shared__ __align__(16) __nv_bfloat16 dbuf[];

    const __nv_bfloat16* src[4];
    src[0] = (const __nv_bfloat16*)Ac;                  // A hi
    src[1] = src[0] + (size_t)M * Kd;                   // A lo
    src[2] = (const __nv_bfloat16*)Bc;                  // B hi
    src[3] = src[2] + (size_t)N * Kd;                   // B lo

    const int tid = threadIdx.x;
    const int bm = blockIdx.y << 7, bn = blockIdx.x << 7;
    const int w = tid >> 5;
    const int wm = (w & 3) * 32;
    const int wn = (w >> 2) * 64;

    const int lr = tid >> 2;
    const int lc = (tid & 3) << 3;

    const int rbase[4] = {bm, bm, bn, bn};

    wmma::fragment<wmma::accumulator, 16, 16, 16, float> acc[2][4];
#pragma unroll
    for (int i = 0; i < 2; i++)
#pragma unroll
        for (int j = 0; j < 4; j++) wmma::fill_fragment(acc[i][j], 0.f);

    const int nk = Kd >> 5;

    // prologue: stage 0
#pragma unroll
    for (int m = 0; m < 4; m++) {
#pragma unroll
        for (int off = 0; off < 128; off += 64) {
            int row = lr + off;
            cp16(dbuf + m * MAT_ELEMS + row * TSTRIDE + lc,
                 src[m] + (size_t)(rbase[m] + row) * Kd + lc);
        }
    }
    cp_commit();

    for (int ki = 0; ki < nk; ki++) {
        int st = ki & 1;
        if (ki + 1 < nk) {
            int ns = (ki + 1) & 1;
            int k0 = (ki + 1) << 5;
#pragma unroll
            for (int m = 0; m < 4; m++) {
#pragma unroll
                for (int off = 0; off < 128; off += 64) {
                    int row = lr + off;
                    cp16(dbuf + (ns * 4 + m) * MAT_ELEMS + row * TSTRIDE + lc,
                         src[m] + (size_t)(rbase[m] + row) * Kd + k0 + lc);
                }
            }
            cp_commit();
            cp_wait<1>();
        } else {
            cp_wait<0>();
        }
        __syncthreads();

        const __nv_bfloat16* tAh = dbuf + (st * 4 + 0) * MAT_ELEMS;
        const __nv_bfloat16* tAl = dbuf + (st * 4 + 1) * MAT_ELEMS;
        const __nv_bfloat16* tBh = dbuf + (st * 4 + 2) * MAT_ELEMS;
        const __nv_bfloat16* tBl = dbuf + (st * 4 + 3) * MAT_ELEMS;

#pragma unroll
        for (int kk = 0; kk < 32; kk += 16) {
            wmma::fragment<wmma::matrix_a, 16, 16, 16, __nv_bfloat16, wmma::row_major> ah[2], al[2];
#pragma unroll
            for (int i = 0; i < 2; i++) {
                wmma::load_matrix_sync(ah[i], tAh + (wm + 16 * i) * TSTRIDE + kk, TSTRIDE);
                wmma::load_matrix_sync(al[i], tAl + (wm + 16 * i) * TSTRIDE + kk, TSTRIDE);
            }
#pragma unroll
            for (int j = 0; j < 4; j++) {
                wmma::fragment<wmma::matrix_b, 16, 16, 16, __nv_bfloat16, wmma::col_major> bh, bl;
                wmma::load_matrix_sync(bh, tBh + (wn + 16 * j) * TSTRIDE + kk, TSTRIDE);
                wmma::load_matrix_sync(bl, tBl + (wn + 16 * j) * TSTRIDE + kk, TSTRIDE);
#pragma unroll
                for (int i = 0; i < 2; i++) {
                    wmma::mma_sync(acc[i][j], ah[i], bh, acc[i][j]);
                    wmma::mma_sync(acc[i][j], ah[i], bl, acc[i][j]);
                    wmma::mma_sync(acc[i][j], al[i], bh, acc[i][j]);
                }
            }
        }
        __syncthreads();
    }
#pragma unroll
    for (int i = 0; i < 2; i++)
#pragma unroll
        for (int j = 0; j < 4; j++) {
            float* cp = C + (size_t)(bm + wm + 16 * i) * N + bn + wn + 16 * j;
            wmma::store_matrix_sync(cp, acc[i][j], N, wmma::mem_row_major);
        }
}

// ==================== elementwise / small kernels ====================
__global__ void k_qproj(const float* __restrict__ ms, const float* __restrict__ wq)
{
    int n = blockIdx.x * blockDim.x + threadIdx.x;
    if (n >= nS * nD) return;
    int s = n / nD, d = n % nD;
    const float* mp = ms + (size_t)s * nD;
    const float* wp = wq + (size_t)d * nD;
    float a = 0.f;
#pragma unroll 4
    for (int e = 0; e < nD; e++) a += mp[e] * wp[e];
    g_q[n] = a;
}

__global__ void k_qwproj(const float* __restrict__ wk)
{
    int n = blockIdx.x * blockDim.x + threadIdx.x;
    if (n >= nS * nHID) return;
    int s = n / nHID, h = n % nHID;
    float a = 0.f;
#pragma unroll 4
    for (int d = 0; d < nD; d++) a += g_q[s * nD + d] * wk[(size_t)d * nHID + h];
    g_qw[n] = a;
}

// causal depthwise conv K=4: 4 timesteps x 2 adjacent channels per thread;
// writes ONLY the bf16 hi/lo image g_cxh1 (fp32 xh1 reconstructed in scan1).
__global__ void k_conv(const float* __restrict__ cw, const float* __restrict__ cb)
{
    int i = blockIdx.x * blockDim.x + threadIdx.x;
    if (i >= (nM / 4) * nHP) return;
    int hp = i % nHP;
    int mq = i / nHP;
    int h  = hp * 2;
    int m0 = mq * 4;
    int t0 = m0 & (nT - 1);
    const float* p = g_proj + (size_t)m0 * nHID2 + nHID + h;
    const long long st = nHID2;
    float2 xv[7];
    const float2 z2 = make_float2(0.f, 0.f);
    xv[0] = (t0 >= 3) ? *(const float2*)(p - 3 * st) : z2;
    xv[1] = (t0 >= 2) ? *(const float2*)(p - 2 * st) : z2;
    xv[2] = (t0 >= 1) ? *(const float2*)(p - 1 * st) : z2;
    xv[3] = *(const float2*)(p);
    xv[4] = *(const float2*)(p + 1 * st);
    xv[5] = *(const float2*)(p + 2 * st);
    xv[6] = *(const float2*)(p + 3 * st);
    float4 wa = *(const float4*)(cw + h * 4);
    float4 wb = *(const float4*)(cw + (h + 1) * 4);
    float2 bb = *(const float2*)(cb + h);
#pragma unroll
    for (int k = 0; k < 4; k++) {
        float o0 = bb.x + wa.x * xv[k].x + wa.y * xv[k + 1].x + wa.z * xv[k + 2].x + wa.w * xv[k + 3].x;
        float o1 = bb.y + wb.x * xv[k].y + wb.y * xv[k + 1].y + wb.z * xv[k + 2].y + wb.w * xv[k + 3].y;
        unsigned hi, lo;
        cvt_pair(o0, o1, hi, lo);
        long long pidx = (long long)(m0 + k) * nHP + hp;
        g_cxh1[pidx] = hi;
        g_cxh1[NPAIRS_H + pidx] = lo;
    }
}

// scan pass 1 with fused alpha/xh2 computation; xh1 reconstructed from bf16 hi+lo
__global__ void k_scan1(const float* __restrict__ fb, const float* __restrict__ gb)
{
    int n = blockIdx.x * blockDim.x + threadIdx.x;
    if (n >= nB * NG * nHID) return;
    int b = n / (NG * nHID);
    int r = n - b * NG * nHID;
    int g = r / nHID;
    int h = r - g * nHID;
    size_t m0 = (size_t)b * nT + (size_t)g * CH;
    float c   = -8.f * log1pf(expf(fb[h]));
    float gbf = gb[h], gbi = gb[nHID + h];
    const bool odd = (h & 1) != 0;
    float A = 1.f, Bv = 0.f;
    size_t idxg = m0 * nHID2 + h;
    size_t idxh = m0 * nHID + h;
    long long pidx = (long long)m0 * nHP + (h >> 1);
#pragma unroll 2
    for (int i = 0; i < CH; i++) {
        float f  = g_gbuf[idxg] + gbf;
        float ip = g_gbuf[idxg + nHID] + gbi;
        unsigned hw = g_cxh1[pidx];
        unsigned lw = g_cxh1[NPAIRS_H + pidx];
        float xh1 = __uint_as_float(odd ? (hw & 0xFFFF0000u) : (hw << 16))
                  + __uint_as_float(odd ? (lw & 0xFFFF0000u) : (lw << 16));
        float sf = 1.f / (1.f + expf(-f));
        float a  = expf(c * sf);
        float si = 1.f / (1.f + expf(-ip));
        float x  = sqrtf(1.f - a * a + 1e-6f) * si * xh1;
        g_alpha[idxh] = a;
        g_xh2[idxh]   = x;
        Bv = a * Bv + x;
        A *= a;
        idxg += nHID2;
        idxh += nHID;
        pidx += nHP;
    }
    g_cA[n] = A; g_cB[n] = Bv;
}

__global__ void k_scan2()
{
    int n = blockIdx.x * blockDim.x + threadIdx.x;
    if (n >= nB * nHID) return;
    int b = n / nHID;
    int h = n - b * nHID;
    float s = 0.f;
    for (int g = 0; g < NG; g++) {
        int j = (b * NG + g) * nHID + h;
        g_carry[j] = s;
        s = g_cA[j] * s + g_cB[j];
    }
}

__global__ void k_scan3()
{
    int n = blockIdx.x * blockDim.x + threadIdx.x;
    if (n >= nB * NG * nHID) return;
    int b = n / (NG * nHID);
    int r = n - b * NG * nHID;
    int g = r / nHID;
    int h = r - g * nHID;
    size_t idx = ((size_t)b * nT + (size_t)g * CH) * nHID + h;
    float run = g_carry[n];
#pragma unroll 4
    for (int i = 0; i < CH; i++) {
        run = g_alpha[idx] * run + g_xh2[idx];
        g_hbuf[idx] = run;
        idx += nHID;
    }
}

// fused: xh3, xr (-> bf16 hi/lo directly), per-token qk dot, per-token wg dot
__global__ __launch_bounds__(256) void k_fuse(const float* __restrict__ wg)
{
    int m = blockIdx.x;
    int tid = threadIdx.x;
    int t = m & (nT - 1);
    int s = t >> 8;
    __shared__ float r1[256], r2[256];
    float qkp = 0.f, xgp = 0.f;
    for (int p = tid; p < nHP; p += 256) {
        int h = 2 * p;
        float2 gt = *(const float2*)(g_proj + (size_t)m * nHID2 + h);
        float2 x2 = *(const float2*)(g_xh2 + (size_t)m * nHID + h);
        float2 hv = *(const float2*)(g_hbuf + (size_t)m * nHID + h);
        float x3a = gt.x * (1.f / (1.f + expf(-gt.x))) * x2.x;
        float x3b = gt.y * (1.f / (1.f + expf(-gt.y))) * x2.y;
        float xra = 0.5f * x3a * (1.f + erff(x3a * 0.7071067811865476f)) * hv.x;
        float xrb = 0.5f * x3b * (1.f + erff(x3b * 0.7071067811865476f)) * hv.y;
        *(float2*)(g_xh3 + (size_t)m * nHID + h) = make_float2(x3a, x3b);
        unsigned hi, lo;
        cvt_pair(xra, xrb, hi, lo);
        long long pidx = (long long)m * nHP + p;
        g_cxr[pidx] = hi;
        g_cxr[NPAIRS_H + pidx] = lo;
        float2 qw2 = *(const float2*)(g_qw + s * nHID + h);
        float2 wg2 = *(const float2*)(wg + h);
        qkp += qw2.x * x3a + qw2.y * x3b;
        xgp += wg2.x * xra + wg2.y * xrb;
    }
    r1[tid] = qkp; r2[tid] = xgp;
    __syncthreads();
    for (int o = 128; o > 0; o >>= 1) {
        if (tid < o) { r1[tid] += r1[tid + o]; r2[tid] += r2[tid + o]; }
        __syncthreads();
    }
    if (tid == 0) { g_qk[m] = r1[0] * INV_SQRT_D; g_xg[m] = r2[0]; }
}

__global__ __launch_bounds__(256) void k_segsoft()
{
    int bs = blockIdx.x;
    int hb = blockIdx.y;
    int tid = threadIdx.x;
    int b = bs >> 4, s = bs & 15;
    size_t base = (size_t)b * nT + (size_t)s * nL;
    __shared__ float at[256];
    __shared__ float red[256];
    float v = g_qk[base + tid];
    red[tid] = v; __syncthreads();
    for (int o = 128; o > 0; o >>= 1) {
        if (tid < o) red[tid] = fmaxf(red[tid], red[tid + o]);
        __syncthreads();
    }
    float mx = red[0];
    __syncthreads();
    float e = expf(v - mx);
    red[tid] = e; __syncthreads();
    for (int o = 128; o > 0; o >>= 1) {
        if (tid < o) red[tid] += red[tid + o];
        __syncthreads();
    }
    at[tid] = e / red[0];
    __syncthreads();
    int h = hb * 256 + tid;
    const float* xp = g_xh3 + base * nHID + h;
    float a0 = 0.f, a1 = 0.f, a2 = 0.f, a3 = 0.f;
    for (int l = 0; l < nL; l += 4) {
        a0 += at[l + 0] * xp[(size_t)(l + 0) * nHID];
        a1 += at[l + 1] * xp[(size_t)(l + 1) * nHID];
        a2 += at[l + 2] * xp[(size_t)(l + 2) * nHID];
        a3 += at[l + 3] * xp[(size_t)(l + 3) * nHID];
    }
    g_u[(size_t)bs * nHID + h] = (a0 + a1) + (a2 + a3);
}

__global__ void k_memproj(const float* __restrict__ wv)
{
    int n = blockIdx.x * blockDim.x + threadIdx.x;
    if (n >= nB * nS * nD) return;
    int bs = n / nD, d = n % nD;
    const float* up = g_u + (size_t)bs * nHID;
    const float* wp = wv + (size_t)d * nHID;
    float a = 0.f;
#pragma unroll 4
    for (int h = 0; h < nHID; h++) a += wp[h] * up[h];
    g_mem[n] = a;
}

__global__ void k_rkproj(const float* __restrict__ rkw)
{
    int n = blockIdx.x * blockDim.x + threadIdx.x;
    if (n >= nB * nS * nD) return;
    int bs = n / nD, d = n % nD;
    const float* mp = g_mem + (size_t)bs * nD;
    const float* wp = rkw + (size_t)d * nD;
    float a = 0.f;
#pragma unroll 4
    for (int e = 0; e < nD; e++) a += mp[e] * wp[e];
    g_rk[n] = a;
}

__global__ void k_rvproj(const float* __restrict__ rvw)
{
    int n = blockIdx.x * blockDim.x + threadIdx.x;
    if (n >= nB * nS * nHID) return;
    int bs = n / nHID, h = n % nHID;
    const float* mp = g_mem + (size_t)bs * nD;
    const float* wp = rvw + (size_t)h * nD;
    float a = 0.f;
#pragma unroll 4
    for (int d = 0; d < nD; d++) a += mp[d] * wp[d];
    g_rv[n] = a;
}

// cross-segment attention + gate; writes bf16 hi/lo (g_cog) directly
__global__ __launch_bounds__(128) void k_attn2()
{
    int m = blockIdx.x;
    int b = m / nT, t = m % nT;
    int seg = t >> 8;
    int tid = threadIdx.x;
    __shared__ float rqs[nD];
    __shared__ float sc[nS];
    __shared__ float a2[nS];
    for (int i = tid; i < nD; i += 128) rqs[i] = g_rq[(size_t)m * nD + i];
    __syncthreads();
    int warp = tid >> 5, lane = tid & 31;
    for (int s = warp; s < nS; s += 4) {
        const float* rkp = g_rk + (size_t)(b * nS + s) * nD;
        float p = 0.f;
        for (int d = lane; d < nD; d += 32) p += rqs[d] * rkp[d];
#pragma unroll
        for (int o = 16; o > 0; o >>= 1) p += __shfl_xor_sync(0xffffffffu, p, o);
        if (lane == 0) sc[s] = p * INV_SQRT_D;
    }
    __syncthreads();
    if (tid == 0) {
        float mx = -1e30f;
        for (int s = seg; s < nS; s++) mx = fmaxf(mx, sc[s]);
        float sum = 0.f;
        for (int s = 0; s < nS; s++) {
            float e = (s >= seg) ? expf(sc[s] - mx) : 0.f;
            a2[s] = e; sum += e;
        }
        float inv = 1.f / sum;
        for (int s = 0; s < nS; s++) a2[s] *= inv;
    }
    __syncthreads();
    float gatev = 1.f / (1.f + expf(-g_xg[m]));
    for (int p = tid; p < nHP; p += 128) {
        int h = 2 * p;
        float aa = 0.f, ab = 0.f;
#pragma unroll
        for (int s = 0; s < nS; s++) {
            float2 rv2 = *(const float2*)(g_rv + (size_t)(b * nS + s) * nHID + h);
            aa += a2[s] * rv2.x;
            ab += a2[s] * rv2.y;
        }
        unsigned hi, lo;
        cvt_pair(gatev * aa, gatev * ab, hi, lo);
        long long pidx = (long long)m * nHP + p;
        g_cog[pidx] = hi;
        g_cog[NPAIRS_H + pidx] = lo;
    }
}

} // namespace lsgm

extern "C" void kernel_launch(void* const* d_in, const int* in_sizes, int n_in,
                              void* d_out, int out_size)
{
    using namespace lsgm;
    const float* x        = (const float*)d_in[0];
    const float* input_w  = (const float*)d_in[1];
    const float* conv_w   = (const float*)d_in[2];
    const float* conv_b   = (const float*)d_in[3];
    const float* gates_w  = (const float*)d_in[4];
    const float* gates_b  = (const float*)d_in[5];
    const float* fbase    = (const float*)d_in[6];
    const float* output_w = (const float*)d_in[7];
    const float* mslots   = (const float*)d_in[8];
    const float* wq_w     = (const float*)d_in[9];
    const float* wk_w     = (const float*)d_in[10];
    const float* wv_w     = (const float*)d_in[11];
    const float* wg_w     = (const float*)d_in[12];
    const float* rq_w     = (const float*)d_in[13];
    const float* rk_w     = (const float*)d_in[14];
    const float* rv_w     = (const float*)d_in[15];
    float* out = (float*)d_out;

    float* proj_p; cudaGetSymbolAddress((void**)&proj_p, g_proj);
    float* gbuf_p; cudaGetSymbolAddress((void**)&gbuf_p, g_gbuf);
    float* rq_p;   cudaGetSymbolAddress((void**)&rq_p,   g_rq);
    unsigned *cx_p, *cxh1_p, *cxr_p, *cog_p, *ciw_p, *cgw_p, *crqw_p, *cow_p;
    cudaGetSymbolAddress((void**)&cx_p,   g_cx);
    cudaGetSymbolAddress((void**)&cxh1_p, g_cxh1);
    cudaGetSymbolAddress((void**)&cxr_p,  g_cxr);
    cudaGetSymbolAddress((void**)&cog_p,  g_cog);
    cudaGetSymbolAddress((void**)&ciw_p,  g_ciw);
    cudaGetSymbolAddress((void**)&cgw_p,  g_cgw);
    cudaGetSymbolAddress((void**)&crqw_p, g_crqw);
    cudaGetSymbolAddress((void**)&cow_p,  g_cow);

    cudaFuncSetAttribute(wgemm, cudaFuncAttributeMaxDynamicSharedMemorySize, WG_SMEM);

    auto cvt = [&](const float* s, unsigned* d, int R, int Kd) {
        long long pairs = (long long)R * Kd / 2;
        k_cvt<<<(unsigned)((pairs + 255) / 256), 256>>>(s, d, pairs);
    };

    // weight conversions + memory-slot query path
    cvt(input_w,  ciw_p,  nHID2, nDIM);
    cvt(gates_w,  cgw_p,  nHID2, nHID);
    cvt(rq_w,     crqw_p, nD,    nHID);
    cvt(output_w, cow_p,  nDIM,  nHID);
    k_qproj <<<(nS * nD + 255) / 256, 256>>>(mslots, wq_w);
    k_qwproj<<<(nS * nHID + 255) / 256, 256>>>(wk_w);

    // proj = x @ input_w^T  -> [M, 3072]
    cvt(x, cx_p, nM, nDIM);
    wgemm<<<dim3(nHID2 / 128, nM / 128), 256, WG_SMEM>>>(cx_p, ciw_p, proj_p, nM, nHID2, nDIM);

    // causal depthwise conv (bf16 hi/lo only)
    k_conv<<<((nM / 4) * nHP + 255) / 256, 256>>>(conv_w, conv_b);

    // gates = xh1 @ gates_w^T (bias folded into scan1) -> [M, 3072]
    wgemm<<<dim3(nHID2 / 128, nM / 128), 256, WG_SMEM>>>(cxh1_p, cgw_p, gbuf_p, nM, nHID2, nHID);

    // chunked scan: pass1 (fused alpha, xh1 from bf16), pass2 (carries), pass3
    k_scan1<<<(nB * NG * nHID) / 256, 256>>>(fbase, gates_b);
    k_scan2<<<(nB * nHID) / 256, 256>>>();
    k_scan3<<<(nB * NG * nHID) / 256, 256>>>();

    // xh3, xr(->bf16), qk dot, wg dot
    k_fuse<<<nM, 256>>>(wg_w);

    // slot attention + tiny projections
    k_segsoft<<<dim3(nB * nS, nHID / 256), 256>>>();
    k_memproj<<<(nB * nS * nD) / 256, 256>>>(wv_w);
    k_rkproj <<<(nB * nS * nD) / 256, 256>>>(rk_w);
    k_rvproj <<<(nB * nS * nHID) / 256, 256>>>(rv_w);

    // rq = xr @ rq_w^T -> [M, 384]
    wgemm<<<dim3(nD / 128, nM / 128), 256, WG_SMEM>>>(cxr_p, crqw_p, rq_p, nM, nD, nHID);

    // cross-segment attention + output gate
    k_attn2<<<nM, 128>>>();

    // final: out = outg @ output_w^T -> [M, 1024]
    wgemm<<<dim3(nDIM / 128, nM / 128), 256, WG_SMEM>>>(cog_p, cow_p, out, nM, nDIM, nHID);
}